// round 5
// baseline (speedup 1.0000x reference)
#include <cuda_runtime.h>
#include <cuda_bf16.h>
#include <cstdint>
#include <cstddef>

// Problem constants: B=8, T=2048, D=1024, KQ=128, topk=8
#define Bz   8
#define Tz   2048
#define Dz   1024
#define KQz  128
#define TOPK 8
#define BT   (Bz * Tz)          // 16384 rows
#define SIM_SCALE 0.08838834764831843f   // 1/sqrt(128)

typedef unsigned long long ull;

// Scratch (device globals: no allocation allowed in kernel_launch)
__device__ float g_q[BT * KQz];      // 8 MB
__device__ float g_k[BT * KQz];      // 8 MB
__device__ int   g_idx[BT * TOPK];   // routed indices for gather

// ---------------------------------------------------------------------------
// f32x2 packed-FMA helpers (FFMA2: 2 fp32 FMAs per instruction)
// ---------------------------------------------------------------------------
__device__ __forceinline__ ull pack2(float a, float b) {
    ull r;
    asm("mov.b64 %0, {%1, %2};" : "=l"(r)
        : "r"(__float_as_uint(a)), "r"(__float_as_uint(b)));
    return r;
}
__device__ __forceinline__ void unpack2(ull v, float& a, float& b) {
    unsigned int lo, hi;
    asm("mov.b64 {%0, %1}, %2;" : "=r"(lo), "=r"(hi) : "l"(v));
    a = __uint_as_float(lo);
    b = __uint_as_float(hi);
}
__device__ __forceinline__ void fma2(ull& d, ull a, ull b) {
    asm("fma.rn.f32x2 %0, %1, %2, %0;" : "+l"(d) : "l"(a), "l"(b));
}
__device__ __forceinline__ float neg_inf() { return __int_as_float(0xff800000); }

// ---------------------------------------------------------------------------
// Kernel 1 (UNCHANGED from round 2 — at fp32 roofline): projection GEMM.
// blockIdx.y = 0 -> Q (Wq,bq), 1 -> K (Wk,bk). 128x128 CTA tile, 8x8/thread.
// ---------------------------------------------------------------------------
__global__ __launch_bounds__(256)
void qk2_kernel(const float* __restrict__ x,
                const float* __restrict__ Wq, const float* __restrict__ bq,
                const float* __restrict__ Wk, const float* __restrict__ bk) {
    __shared__ float xs[32 * 132];   // [k][row], stride 132
    __shared__ float ws[32 * 132];   // [k][col], stride 132

    const float* W    = blockIdx.y ? Wk : Wq;
    const float* bias = blockIdx.y ? bk : bq;
    float* outp       = blockIdx.y ? g_k : g_q;

    const int tid  = threadIdx.x;
    const int tx   = tid & 15;
    const int ty   = tid >> 4;
    const int row0 = blockIdx.x * 128;

    int c4a[4], ra[4];
#pragma unroll
    for (int i = 0; i < 4; i++) {
        int s = tid + i * 256;
        c4a[i] = (s & 1) + (((s >> 5) & 3) << 1);
        ra[i]  = ((s >> 1) & 15) + ((s >> 7) << 4);
    }

    ull acc[8][4];
#pragma unroll
    for (int i = 0; i < 8; i++)
#pragma unroll
        for (int j = 0; j < 4; j++) acc[i][j] = 0ull;

    float4 px[4], pw[4];
#pragma unroll
    for (int i = 0; i < 4; i++) {
        px[i] = *(const float4*)&x[(size_t)(row0 + ra[i]) * Dz + c4a[i] * 4];
        pw[i] = *(const float4*)&W[(size_t)ra[i] * Dz + c4a[i] * 4];
    }

    for (int kb = 0; kb < 32; kb++) {
#pragma unroll
        for (int i = 0; i < 4; i++) {
            int kbase = c4a[i] * 4, r = ra[i];
            xs[(kbase + 0) * 132 + r] = px[i].x; xs[(kbase + 1) * 132 + r] = px[i].y;
            xs[(kbase + 2) * 132 + r] = px[i].z; xs[(kbase + 3) * 132 + r] = px[i].w;
            ws[(kbase + 0) * 132 + r] = pw[i].x; ws[(kbase + 1) * 132 + r] = pw[i].y;
            ws[(kbase + 2) * 132 + r] = pw[i].z; ws[(kbase + 3) * 132 + r] = pw[i].w;
        }
        __syncthreads();

        if (kb < 31) {
            int koff = (kb + 1) * 32;
#pragma unroll
            for (int i = 0; i < 4; i++) {
                px[i] = *(const float4*)&x[(size_t)(row0 + ra[i]) * Dz + koff + c4a[i] * 4];
                pw[i] = *(const float4*)&W[(size_t)ra[i] * Dz + koff + c4a[i] * 4];
            }
        }

#pragma unroll 8
        for (int kk = 0; kk < 32; kk++) {
            float4 a0 = *(const float4*)&xs[kk * 132 + ty * 8];
            float4 a1 = *(const float4*)&xs[kk * 132 + ty * 8 + 4];
            ull ap[8] = { pack2(a0.x, a0.x), pack2(a0.y, a0.y),
                          pack2(a0.z, a0.z), pack2(a0.w, a0.w),
                          pack2(a1.x, a1.x), pack2(a1.y, a1.y),
                          pack2(a1.z, a1.z), pack2(a1.w, a1.w) };
            ulonglong2 b0 = *(const ulonglong2*)&ws[kk * 132 + tx * 8];
            ulonglong2 b1 = *(const ulonglong2*)&ws[kk * 132 + tx * 8 + 4];
            ull bp[4] = { b0.x, b0.y, b1.x, b1.y };
#pragma unroll
            for (int i = 0; i < 8; i++)
#pragma unroll
                for (int j = 0; j < 4; j++) fma2(acc[i][j], ap[i], bp[j]);
        }
        __syncthreads();
    }

    float bv[8];
#pragma unroll
    for (int j = 0; j < 8; j++) bv[j] = bias[tx * 8 + j];

#pragma unroll
    for (int i = 0; i < 8; i++) {
        float o[8];
#pragma unroll
        for (int j = 0; j < 4; j++) unpack2(acc[i][j], o[2 * j], o[2 * j + 1]);
        int grow = row0 + ty * 8 + i;
        float4 s0 = { o[0] + bv[0], o[1] + bv[1], o[2] + bv[2], o[3] + bv[3] };
        float4 s1 = { o[4] + bv[4], o[5] + bv[5], o[6] + bv[6], o[7] + bv[7] };
        *(float4*)&outp[(size_t)grow * KQz + tx * 8]     = s0;
        *(float4*)&outp[(size_t)grow * KQz + tx * 8 + 4] = s1;
    }
}

// ---------------------------------------------------------------------------
// top-K insertion (sorted desc; ascending-index feed => stable ties)
// ---------------------------------------------------------------------------
template <int KD>
__device__ __forceinline__ void topk_insert(float v, int i,
                                            float (&tv)[KD], int (&ti)[KD]) {
    if (v > tv[KD - 1]) {
        float pv = v; int pi = i;
#pragma unroll
        for (int p = 0; p < KD; p++) {
            if (pv > tv[p]) {
                float t = tv[p]; int u = ti[p];
                tv[p] = pv; ti[p] = pi;
                pv = t; pi = u;
            }
        }
    }
}

// ---------------------------------------------------------------------------
// mma.sync bf16 helpers (generic PTX — HMMA fallback on sm_103a)
// ---------------------------------------------------------------------------
__device__ __forceinline__ void ldsm_x4(uint32_t& r0, uint32_t& r1,
                                        uint32_t& r2, uint32_t& r3,
                                        uint32_t addr) {
    asm volatile("ldmatrix.sync.aligned.m8n8.x4.shared.b16 {%0,%1,%2,%3}, [%4];"
                 : "=r"(r0), "=r"(r1), "=r"(r2), "=r"(r3) : "r"(addr));
}
__device__ __forceinline__ void mma_bf16(float (&d)[4], const uint32_t (&a)[4],
                                         uint32_t b0, uint32_t b1) {
    asm volatile(
        "mma.sync.aligned.m16n8k16.row.col.f32.bf16.bf16.f32 "
        "{%0,%1,%2,%3}, {%4,%5,%6,%7}, {%8,%9}, {%0,%1,%2,%3};"
        : "+f"(d[0]), "+f"(d[1]), "+f"(d[2]), "+f"(d[3])
        : "r"(a[0]), "r"(a[1]), "r"(a[2]), "r"(a[3]), "r"(b0), "r"(b1));
}
__device__ __forceinline__ uint32_t smem_u32(const void* p) {
    uint32_t a;
    asm("{ .reg .u64 t; cvta.to.shared.u64 t, %1; cvt.u32.u64 %0, t; }"
        : "=r"(a) : "l"(p));
    return a;
}

// ---------------------------------------------------------------------------
// Kernel 2: bf16-HMMA screening (top-16 per key-half per row) + exact fp32
// rescore of the 32 candidates. CTA: 128 q-rows, 256 threads (8 warps).
// Warp tile: 32 rows x 64 keys. Key chunks of 128, 16 chunks per batch.
// smem rows padded to 272 B -> ldmatrix phases hit all 32 banks.
// ---------------------------------------------------------------------------
#define QB_OFF  0
#define KB_OFF  34816                    // 128 * 272
#define ST_OFF  69632                    // + 128 * 272
#define K2_SMEM (ST_OFF + 128 * 132 * 4) // + 67584 = 137216

__global__ __launch_bounds__(256)
void screen_topk_kernel(float* __restrict__ out_idx, float* __restrict__ out_sim) {
    extern __shared__ char smem[];
    char*  Qb = smem + QB_OFF;           // bf16 [128][136], 272 B/row
    char*  Kb = smem + KB_OFF;           // bf16 [128][136]
    float* St = (float*)(smem + ST_OFF); // f32 [128][132] stage / cand buffer

    const int tid  = threadIdx.x;
    const int wid  = tid >> 5;
    const int lane = tid & 31;
    const int row0 = blockIdx.x * 128;
    const int b    = row0 >> 11;
    const int key0 = b * Tz;

    const int wm = wid >> 1;             // warp row group: 32 rows
    const int wn = wid & 1;              // warp key group: 64 keys

    // convert Q tile [128 rows x 128 dims] f32 -> bf16 (row-major, 272 B rows)
#pragma unroll
    for (int it = 0; it < 16; it++) {
        int idx = tid + it * 256;
        int r = idx >> 5, g = idx & 31;
        float4 v = *(const float4*)&g_q[(size_t)(row0 + r) * KQz + g * 4];
        __nv_bfloat162 lo = { __float2bfloat16_rn(v.x), __float2bfloat16_rn(v.y) };
        __nv_bfloat162 hi = { __float2bfloat16_rn(v.z), __float2bfloat16_rn(v.w) };
        *(__nv_bfloat162*)(Qb + r * 272 + g * 8)     = lo;
        *(__nv_bfloat162*)(Qb + r * 272 + g * 8 + 4) = hi;
    }

    float tv[16]; int ti[16];
#pragma unroll
    for (int p = 0; p < 16; p++) { tv[p] = neg_inf(); ti[p] = 0x7fffffff; }
    const int srow  = tid >> 1;          // scan row
    const int shalf = tid & 1;           // scan key half (64 keys)

    const uint32_t qbase = smem_u32(Qb) + wm * 32 * 272;
    const uint32_t kbase = smem_u32(Kb) + wn * 64 * 272;
    // ldmatrix lane offsets
    const uint32_t a_lo = (uint32_t)(lane & 15) * 272 + ((lane >> 4) << 4);
    const uint32_t b_lo = (uint32_t)((lane & 7) + ((lane >> 4) << 3)) * 272 +
                          (((lane >> 3) & 1) << 4);

    for (int c = 0; c < 16; c++) {
        // convert K chunk [128 keys x 128 dims] -> bf16
#pragma unroll
        for (int it = 0; it < 16; it++) {
            int idx = tid + it * 256;
            int r = idx >> 5, g = idx & 31;
            float4 v = *(const float4*)&g_k[(size_t)(key0 + c * 128 + r) * KQz + g * 4];
            __nv_bfloat162 lo = { __float2bfloat16_rn(v.x), __float2bfloat16_rn(v.y) };
            __nv_bfloat162 hi = { __float2bfloat16_rn(v.z), __float2bfloat16_rn(v.w) };
            *(__nv_bfloat162*)(Kb + r * 272 + g * 8)     = lo;
            *(__nv_bfloat162*)(Kb + r * 272 + g * 8 + 4) = hi;
        }
        __syncthreads();

        float acc[2][8][4];
#pragma unroll
        for (int mt = 0; mt < 2; mt++)
#pragma unroll
            for (int nt = 0; nt < 8; nt++)
#pragma unroll
                for (int j = 0; j < 4; j++) acc[mt][nt][j] = 0.0f;

#pragma unroll
        for (int ks = 0; ks < 8; ks++) {
            uint32_t a[2][4];
#pragma unroll
            for (int mt = 0; mt < 2; mt++)
                ldsm_x4(a[mt][0], a[mt][1], a[mt][2], a[mt][3],
                        qbase + mt * (16 * 272) + ks * 32 + a_lo);
#pragma unroll
            for (int np = 0; np < 4; np++) {
                uint32_t b0, b1, b2, b3;
                ldsm_x4(b0, b1, b2, b3,
                        kbase + np * (16 * 272) + ks * 32 + b_lo);
                mma_bf16(acc[0][2 * np],     a[0], b0, b1);
                mma_bf16(acc[0][2 * np + 1], a[0], b2, b3);
                mma_bf16(acc[1][2 * np],     a[1], b0, b1);
                mma_bf16(acc[1][2 * np + 1], a[1], b2, b3);
            }
        }

        // stage accumulators -> St[row][key] (raw bf16 dot, unscaled)
#pragma unroll
        for (int mt = 0; mt < 2; mt++) {
            int rb = wm * 32 + mt * 16 + (lane >> 2);
#pragma unroll
            for (int nt = 0; nt < 8; nt++) {
                int kcol = wn * 64 + nt * 8 + 2 * (lane & 3);
                *(float2*)&St[rb * 132 + kcol] =
                    make_float2(acc[mt][nt][0], acc[mt][nt][1]);
                *(float2*)&St[(rb + 8) * 132 + kcol] =
                    make_float2(acc[mt][nt][2], acc[mt][nt][3]);
            }
        }
        __syncthreads();

        // streaming screen: 2 threads per row, 64 keys each, ascending idx
        {
            const float* sp = &St[srow * 132 + shalf * 64];
            int kb = c * 128 + shalf * 64;
#pragma unroll
            for (int q = 0; q < 16; q++) {
                float4 v = *(const float4*)&sp[q * 4];
                topk_insert<16>(v.x, kb + q * 4 + 0, tv, ti);
                topk_insert<16>(v.y, kb + q * 4 + 1, tv, ti);
                topk_insert<16>(v.z, kb + q * 4 + 2, tv, ti);
                topk_insert<16>(v.w, kb + q * 4 + 3, tv, ti);
            }
        }
        __syncthreads();   // scans done before next chunk's conversions/mma
    }

    // dump candidate indices: cand[row][32] over St region
    int* ci = (int*)St;                  // [128][32]
#pragma unroll
    for (int p = 0; p < 16; p++) ci[srow * 32 + shalf * 16 + p] = ti[p];
    __syncthreads();

    // exact fp32 rescore: warp w -> rows w*16..+15, lane -> candidate
    for (int rr = 0; rr < 16; rr++) {
        int r = wid * 16 + rr;
        int cj = ci[r * 32 + lane];
        const float* qp = &g_q[(size_t)(row0 + r) * KQz];
        const float* kp = &g_k[(size_t)(key0 + cj) * KQz];
        float s0 = 0.f, s1 = 0.f, s2 = 0.f, s3 = 0.f;
#pragma unroll
        for (int d = 0; d < 32; d += 4) {
            float4 qv0 = *(const float4*)&qp[d * 4];
            float4 kv0 = *(const float4*)&kp[d * 4];
            float4 qv1 = *(const float4*)&qp[d * 4 + 4];
            float4 kv1 = *(const float4*)&kp[d * 4 + 4];
            float4 qv2 = *(const float4*)&qp[d * 4 + 8];
            float4 kv2 = *(const float4*)&kp[d * 4 + 8];
            float4 qv3 = *(const float4*)&qp[d * 4 + 12];
            float4 kv3 = *(const float4*)&kp[d * 4 + 12];
            s0 += qv0.x * kv0.x + qv0.y * kv0.y + qv0.z * kv0.z + qv0.w * kv0.w;
            s1 += qv1.x * kv1.x + qv1.y * kv1.y + qv1.z * kv1.z + qv1.w * kv1.w;
            s2 += qv2.x * kv2.x + qv2.y * kv2.y + qv2.z * kv2.z + qv2.w * kv2.w;
            s3 += qv3.x * kv3.x + qv3.y * kv3.y + qv3.z * kv3.z + qv3.w * kv3.w;
        }
        float val = ((s0 + s1) + (s2 + s3)) * SIM_SCALE;

        // warp-wide exact ranking (desc value, asc index on ties)
        int rank = 0;
#pragma unroll
        for (int s = 0; s < 32; s++) {
            float vs = __shfl_sync(0xffffffffu, val, s);
            int   is = __shfl_sync(0xffffffffu, cj, s);
            rank += (vs > val) || (vs == val && is < cj);
        }
        if (rank < TOPK) {
            int grow = row0 + r;
            out_idx[(size_t)grow * TOPK + rank] = (float)cj;
            out_sim[(size_t)grow * TOPK + rank] = val;
            g_idx [(size_t)grow * TOPK + rank] = cj;
        }
    }
}

// ---------------------------------------------------------------------------
// Kernel 3: gather routed tokens. One CTA per query row; warp w copies pick w.
// Streaming stores keep L2 for the (reused) source rows.
// ---------------------------------------------------------------------------
__global__ __launch_bounds__(256)
void gather_kernel(const float* __restrict__ x, float* __restrict__ out) {
    const int row  = blockIdx.x;
    const int w    = threadIdx.x >> 5;
    const int lane = threadIdx.x & 31;
    const int job  = row * TOPK + w;
    const int b    = row >> 11;
    const int idx  = g_idx[job];
    const float4* src = (const float4*)(x + (size_t)(b * Tz + idx) * Dz);
    float4* dst = (float4*)(out + (size_t)job * Dz);
#pragma unroll
    for (int j = 0; j < 8; j++) __stcs(&dst[j * 32 + lane], src[j * 32 + lane]);
}

// ---------------------------------------------------------------------------
extern "C" void kernel_launch(void* const* d_in, const int* in_sizes, int n_in,
                              void* d_out, int out_size) {
    const float* x  = (const float*)d_in[0];
    const float* Wq = (const float*)d_in[1];
    const float* bq = (const float*)d_in[2];
    const float* Wk = (const float*)d_in[3];
    const float* bk = (const float*)d_in[4];

    float* out      = (float*)d_out;
    float* out_g    = out;                                   // [B,T,8,D]
    float* out_idx  = out + (size_t)BT * TOPK * Dz;          // [B,T,8] as float
    float* out_sim  = out_idx + (size_t)BT * TOPK;           // [B,T,8]

    cudaFuncSetAttribute(screen_topk_kernel,
                         cudaFuncAttributeMaxDynamicSharedMemorySize, K2_SMEM);

    qk2_kernel<<<dim3(BT / 128, 2), 256>>>(x, Wq, bq, Wk, bk);
    screen_topk_kernel<<<BT / 128, 256, K2_SMEM>>>(out_idx, out_sim);
    gather_kernel<<<BT, 256>>>(x, out_g);
}

// round 7
// speedup vs baseline: 1.1309x; 1.1309x over previous
#include <cuda_runtime.h>
#include <cuda_bf16.h>
#include <cstdint>
#include <cstddef>

// Problem constants: B=8, T=2048, D=1024, KQ=128, topk=8
#define Bz   8
#define Tz   2048
#define Dz   1024
#define KQz  128
#define TOPK 8
#define BT   (Bz * Tz)          // 16384 rows
#define SIM_SCALE 0.08838834764831843f   // 1/sqrt(128)

typedef unsigned long long ull;

// Scratch (device globals: no allocation allowed in kernel_launch)
__device__ float g_q[BT * KQz];      // 8 MB
__device__ float g_k[BT * KQz];      // 8 MB
__device__ int   g_idx[BT * TOPK];   // routed indices for gather

// ---------------------------------------------------------------------------
// f32x2 packed-FMA helpers (FFMA2: 2 fp32 FMAs per instruction)
// ---------------------------------------------------------------------------
__device__ __forceinline__ ull pack2(float a, float b) {
    ull r;
    asm("mov.b64 %0, {%1, %2};" : "=l"(r)
        : "r"(__float_as_uint(a)), "r"(__float_as_uint(b)));
    return r;
}
__device__ __forceinline__ void unpack2(ull v, float& a, float& b) {
    unsigned int lo, hi;
    asm("mov.b64 {%0, %1}, %2;" : "=r"(lo), "=r"(hi) : "l"(v));
    a = __uint_as_float(lo);
    b = __uint_as_float(hi);
}
__device__ __forceinline__ void fma2(ull& d, ull a, ull b) {
    asm("fma.rn.f32x2 %0, %1, %2, %0;" : "+l"(d) : "l"(a), "l"(b));
}
__device__ __forceinline__ float neg_inf() { return __int_as_float(0xff800000); }

// ---------------------------------------------------------------------------
// Kernel 1 (UNCHANGED — at fp32 roofline, 67.4 TF/s measured): projection GEMM.
// blockIdx.y = 0 -> Q (Wq,bq), 1 -> K (Wk,bk). 128x128 CTA tile, 8x8/thread.
// ---------------------------------------------------------------------------
__global__ __launch_bounds__(256)
void qk2_kernel(const float* __restrict__ x,
                const float* __restrict__ Wq, const float* __restrict__ bq,
                const float* __restrict__ Wk, const float* __restrict__ bk) {
    __shared__ float xs[32 * 132];   // [k][row], stride 132
    __shared__ float ws[32 * 132];   // [k][col], stride 132

    const float* W    = blockIdx.y ? Wk : Wq;
    const float* bias = blockIdx.y ? bk : bq;
    float* outp       = blockIdx.y ? g_k : g_q;

    const int tid  = threadIdx.x;
    const int tx   = tid & 15;
    const int ty   = tid >> 4;
    const int row0 = blockIdx.x * 128;

    int c4a[4], ra[4];
#pragma unroll
    for (int i = 0; i < 4; i++) {
        int s = tid + i * 256;
        c4a[i] = (s & 1) + (((s >> 5) & 3) << 1);
        ra[i]  = ((s >> 1) & 15) + ((s >> 7) << 4);
    }

    ull acc[8][4];
#pragma unroll
    for (int i = 0; i < 8; i++)
#pragma unroll
        for (int j = 0; j < 4; j++) acc[i][j] = 0ull;

    float4 px[4], pw[4];
#pragma unroll
    for (int i = 0; i < 4; i++) {
        px[i] = *(const float4*)&x[(size_t)(row0 + ra[i]) * Dz + c4a[i] * 4];
        pw[i] = *(const float4*)&W[(size_t)ra[i] * Dz + c4a[i] * 4];
    }

    for (int kb = 0; kb < 32; kb++) {
#pragma unroll
        for (int i = 0; i < 4; i++) {
            int kbase = c4a[i] * 4, r = ra[i];
            xs[(kbase + 0) * 132 + r] = px[i].x; xs[(kbase + 1) * 132 + r] = px[i].y;
            xs[(kbase + 2) * 132 + r] = px[i].z; xs[(kbase + 3) * 132 + r] = px[i].w;
            ws[(kbase + 0) * 132 + r] = pw[i].x; ws[(kbase + 1) * 132 + r] = pw[i].y;
            ws[(kbase + 2) * 132 + r] = pw[i].z; ws[(kbase + 3) * 132 + r] = pw[i].w;
        }
        __syncthreads();

        if (kb < 31) {
            int koff = (kb + 1) * 32;
#pragma unroll
            for (int i = 0; i < 4; i++) {
                px[i] = *(const float4*)&x[(size_t)(row0 + ra[i]) * Dz + koff + c4a[i] * 4];
                pw[i] = *(const float4*)&W[(size_t)ra[i] * Dz + koff + c4a[i] * 4];
            }
        }

#pragma unroll 8
        for (int kk = 0; kk < 32; kk++) {
            float4 a0 = *(const float4*)&xs[kk * 132 + ty * 8];
            float4 a1 = *(const float4*)&xs[kk * 132 + ty * 8 + 4];
            ull ap[8] = { pack2(a0.x, a0.x), pack2(a0.y, a0.y),
                          pack2(a0.z, a0.z), pack2(a0.w, a0.w),
                          pack2(a1.x, a1.x), pack2(a1.y, a1.y),
                          pack2(a1.z, a1.z), pack2(a1.w, a1.w) };
            ulonglong2 b0 = *(const ulonglong2*)&ws[kk * 132 + tx * 8];
            ulonglong2 b1 = *(const ulonglong2*)&ws[kk * 132 + tx * 8 + 4];
            ull bp[4] = { b0.x, b0.y, b1.x, b1.y };
#pragma unroll
            for (int i = 0; i < 8; i++)
#pragma unroll
                for (int j = 0; j < 4; j++) fma2(acc[i][j], ap[i], bp[j]);
        }
        __syncthreads();
    }

    float bv[8];
#pragma unroll
    for (int j = 0; j < 8; j++) bv[j] = bias[tx * 8 + j];

#pragma unroll
    for (int i = 0; i < 8; i++) {
        float o[8];
#pragma unroll
        for (int j = 0; j < 4; j++) unpack2(acc[i][j], o[2 * j], o[2 * j + 1]);
        int grow = row0 + ty * 8 + i;
        float4 s0 = { o[0] + bv[0], o[1] + bv[1], o[2] + bv[2], o[3] + bv[3] };
        float4 s1 = { o[4] + bv[4], o[5] + bv[5], o[6] + bv[6], o[7] + bv[7] };
        *(float4*)&outp[(size_t)grow * KQz + tx * 8]     = s0;
        *(float4*)&outp[(size_t)grow * KQz + tx * 8 + 4] = s1;
    }
}

// ---------------------------------------------------------------------------
// top-8 insertion (sorted desc; ascending-index feed => stable ties)
// ---------------------------------------------------------------------------
__device__ __forceinline__ void topk_insert(float v, int i,
                                            float (&tv)[8], int (&ti)[8]) {
    if (v > tv[7]) {
        float pv = v; int pi = i;
#pragma unroll
        for (int p = 0; p < 8; p++) {
            if (pv > tv[p]) {
                float t = tv[p]; int u = ti[p];
                tv[p] = pv; ti[p] = pi;
                pv = t; pi = u;
            }
        }
    }
}

// ---------------------------------------------------------------------------
// Kernel 2: sim = (Q @ K^T) * scale, fused streaming exact top-8.
// CTA: 128 q-rows x 128-key chunks (16 chunks), 256 threads, 8x8 tiles
// (identical mainloop structure to qk2 -> same measured FFMA2 efficiency).
// Per chunk: GEMM -> stage scaled tile into smem (overlay K buf) -> 2 threads
// per row scan halves with float4 group-max prefilter -> xor-1 shuffle merge.
// ---------------------------------------------------------------------------
#define K2_SMEM (2 * 128 * 132 * 4)   // Qs + Ks(/stage) = 135168 B

__global__ __launch_bounds__(256)
void sim_topk_kernel(float* __restrict__ out_idx, float* __restrict__ out_sim) {
    extern __shared__ float sm[];
    float* Qs = sm;                // [128 d][132]  (128 rows + pad)
    float* Ks = sm + 128 * 132;    // [128 d][132]  (128 keys + pad); stage reuse

    const int tid  = threadIdx.x;
    const int tx   = tid & 15;        // 8 keys each  -> 128 keys
    const int ty   = tid >> 4;        // 8 rows each  -> 128 rows
    const int row0 = blockIdx.x * 128;
    const int b    = row0 >> 11;
    const int key0 = b * Tz;

    // load Q tile [128 rows x 128 d] transposed, conflict-free decomposition
#pragma unroll
    for (int i = 0; i < 16; i++) {
        int s  = tid + i * 256;
        int c4 = (s & 1) + (((s >> 5) & 15) << 1);    // [0,32)
        int r  = ((s >> 1) & 15) + ((s >> 9) << 4);   // [0,128)
        float4 v = *(const float4*)&g_q[(size_t)(row0 + r) * KQz + c4 * 4];
        Qs[(c4 * 4 + 0) * 132 + r] = v.x; Qs[(c4 * 4 + 1) * 132 + r] = v.y;
        Qs[(c4 * 4 + 2) * 132 + r] = v.z; Qs[(c4 * 4 + 3) * 132 + r] = v.w;
    }

    float tv[8]; int ti[8];
#pragma unroll
    for (int p = 0; p < 8; p++) { tv[p] = neg_inf(); ti[p] = 0x7fffffff; }

    const int srow  = tid >> 1;       // scan row [0,128)
    const int shalf = tid & 1;        // scan half: keys [h*64, h*64+64)

    for (int kb = 0; kb < 16; kb++) {
        // load K chunk [128 keys x 128 d] transposed (Ks free: prev scan synced)
#pragma unroll
        for (int i = 0; i < 16; i++) {
            int s  = tid + i * 256;
            int c4 = (s & 1) + (((s >> 5) & 15) << 1);
            int t  = ((s >> 1) & 15) + ((s >> 9) << 4);
            float4 v = *(const float4*)&g_k[(size_t)(key0 + kb * 128 + t) * KQz + c4 * 4];
            Ks[(c4 * 4 + 0) * 132 + t] = v.x; Ks[(c4 * 4 + 1) * 132 + t] = v.y;
            Ks[(c4 * 4 + 2) * 132 + t] = v.z; Ks[(c4 * 4 + 3) * 132 + t] = v.w;
        }
        __syncthreads();   // covers Qs stores on kb==0 too

        ull acc[8][4];
#pragma unroll
        for (int i = 0; i < 8; i++)
#pragma unroll
            for (int j = 0; j < 4; j++) acc[i][j] = 0ull;

#pragma unroll 8
        for (int d = 0; d < 128; d++) {
            float4 a0 = *(const float4*)&Qs[d * 132 + ty * 8];
            float4 a1 = *(const float4*)&Qs[d * 132 + ty * 8 + 4];
            ull ap[8] = { pack2(a0.x, a0.x), pack2(a0.y, a0.y),
                          pack2(a0.z, a0.z), pack2(a0.w, a0.w),
                          pack2(a1.x, a1.x), pack2(a1.y, a1.y),
                          pack2(a1.z, a1.z), pack2(a1.w, a1.w) };
            ulonglong2 b0 = *(const ulonglong2*)&Ks[d * 132 + tx * 8];
            ulonglong2 b1 = *(const ulonglong2*)&Ks[d * 132 + tx * 8 + 4];
            ull bp[4] = { b0.x, b0.y, b1.x, b1.y };
#pragma unroll
            for (int i = 0; i < 8; i++)
#pragma unroll
                for (int j = 0; j < 4; j++) fma2(acc[i][j], ap[i], bp[j]);
        }
        __syncthreads();   // all reads of Ks done before overlay

        // stage scaled sim tile into Ks region: St[row][key], stride 132
#pragma unroll
        for (int i = 0; i < 8; i++) {
            float o[8];
#pragma unroll
            for (int j = 0; j < 4; j++) unpack2(acc[i][j], o[2 * j], o[2 * j + 1]);
            int r = ty * 8 + i;
            float4 s0 = { o[0] * SIM_SCALE, o[1] * SIM_SCALE,
                          o[2] * SIM_SCALE, o[3] * SIM_SCALE };
            float4 s1 = { o[4] * SIM_SCALE, o[5] * SIM_SCALE,
                          o[6] * SIM_SCALE, o[7] * SIM_SCALE };
            *(float4*)&Ks[r * 132 + tx * 8]     = s0;
            *(float4*)&Ks[r * 132 + tx * 8 + 4] = s1;
        }
        __syncthreads();

        // scan: 2 threads per row, 64 keys each, group-max prefilter,
        // ascending index feed (stable ties)
        {
            const float* sp = &Ks[srow * 132 + shalf * 64];
            int kbase = kb * 128 + shalf * 64;
#pragma unroll
            for (int q = 0; q < 16; q++) {
                float4 v = *(const float4*)&sp[q * 4];
                float m = fmaxf(fmaxf(v.x, v.y), fmaxf(v.z, v.w));
                if (m > tv[7]) {
                    topk_insert(v.x, kbase + q * 4 + 0, tv, ti);
                    topk_insert(v.y, kbase + q * 4 + 1, tv, ti);
                    topk_insert(v.z, kbase + q * 4 + 2, tv, ti);
                    topk_insert(v.w, kbase + q * 4 + 3, tv, ti);
                }
            }
        }
        __syncthreads();   // scan done before next chunk overwrites Ks
    }

    // merge the two half-lists of each row (threads tid, tid^1, same warp)
    const bool lead = (tid & 1) == 0;
    const int grow = row0 + srow;
    for (int r = 0; r < 8; r++) {
        float v = tv[0]; int i = ti[0];
        float ov = __shfl_xor_sync(0xffffffffu, v, 1);
        int   oi = __shfl_xor_sync(0xffffffffu, i, 1);
        bool take_other = (ov > v) || (ov == v && oi < i);
        float wv = take_other ? ov : v;
        int   wi = take_other ? oi : i;
        if (!take_other) {   // my head won: pop (static shift -> stays in regs)
#pragma unroll
            for (int p = 0; p < 7; p++) { tv[p] = tv[p + 1]; ti[p] = ti[p + 1]; }
            tv[7] = neg_inf(); ti[7] = 0x7fffffff;
        }
        if (lead) {
            out_idx[(size_t)grow * TOPK + r] = (float)wi;
            out_sim[(size_t)grow * TOPK + r] = wv;
            g_idx [(size_t)grow * TOPK + r] = wi;
        }
    }
}

// ---------------------------------------------------------------------------
// Kernel 3: gather routed tokens. One CTA per query row; warp w copies pick w.
// Streaming stores keep L2 for the (reused) source rows.
// ---------------------------------------------------------------------------
__global__ __launch_bounds__(256)
void gather_kernel(const float* __restrict__ x, float* __restrict__ out) {
    const int row  = blockIdx.x;
    const int w    = threadIdx.x >> 5;
    const int lane = threadIdx.x & 31;
    const int job  = row * TOPK + w;
    const int b    = row >> 11;
    const int idx  = g_idx[job];
    const float4* src = (const float4*)(x + (size_t)(b * Tz + idx) * Dz);
    float4* dst = (float4*)(out + (size_t)job * Dz);
#pragma unroll
    for (int j = 0; j < 8; j++) __stcs(&dst[j * 32 + lane], src[j * 32 + lane]);
}

// ---------------------------------------------------------------------------
extern "C" void kernel_launch(void* const* d_in, const int* in_sizes, int n_in,
                              void* d_out, int out_size) {
    const float* x  = (const float*)d_in[0];
    const float* Wq = (const float*)d_in[1];
    const float* bq = (const float*)d_in[2];
    const float* Wk = (const float*)d_in[3];
    const float* bk = (const float*)d_in[4];

    float* out      = (float*)d_out;
    float* out_g    = out;                                   // [B,T,8,D]
    float* out_idx  = out + (size_t)BT * TOPK * Dz;          // [B,T,8] as float
    float* out_sim  = out_idx + (size_t)BT * TOPK;           // [B,T,8]

    cudaFuncSetAttribute(sim_topk_kernel,
                         cudaFuncAttributeMaxDynamicSharedMemorySize, K2_SMEM);

    qk2_kernel<<<dim3(BT / 128, 2), 256>>>(x, Wq, bq, Wk, bk);
    sim_topk_kernel<<<BT / 128, 256, K2_SMEM>>>(out_idx, out_sim);
    gather_kernel<<<BT, 256>>>(x, out_g);
}